// round 1
// baseline (speedup 1.0000x reference)
#include <cuda_runtime.h>
#include <cuda_bf16.h>
#include <math.h>

#define NQ 128
#define ND 1024
#define DD 256
#define CAT 512

// ---------------- device scratch ----------------
__device__ float g_qA[NQ * CAT];
__device__ float g_qB[NQ * CAT];
__device__ float g_dA[ND * CAT];
__device__ float g_dB[ND * CAT];
__device__ float g_qh[NQ * DD];
__device__ float g_dh[ND * DD];
__device__ float g_qdeg[NQ];
__device__ float g_ddeg[ND];
__device__ float g_qnorm[NQ];
__device__ float g_dnorm[ND];
__device__ float g_cosw[8192];
__device__ float g_Bq[NQ * DD];
__device__ float g_Bd[ND * DD];

// ---------------- generic register-tiled GEMM ----------------
// C[M,N] = A[M,K] @ B[K,N] (+ bias), row-major, M%64==0, N%64==0, K%16==0
__global__ void gemm_rt(const float* __restrict__ A, int lda,
                        const float* __restrict__ B, int ldb,
                        float* __restrict__ C, int ldc,
                        const float* __restrict__ bias,
                        int M, int N, int K)
{
    __shared__ float As[16][65];
    __shared__ float Bs[16][65];
    int t  = threadIdx.x;
    int tx = t & 15, ty = t >> 4;
    int m0 = blockIdx.y * 64, n0 = blockIdx.x * 64;
    float acc[4][4] = {};
    for (int k0 = 0; k0 < K; k0 += 16) {
        {
            int r  = t >> 2;          // 0..63
            int kk = (t & 3) * 4;     // 0,4,8,12
            const float* Ap = A + (size_t)(m0 + r) * lda + k0 + kk;
            #pragma unroll
            for (int u = 0; u < 4; u++) As[kk + u][r] = Ap[u];
        }
        {
            int r  = t >> 4;          // 0..15
            int nn = (t & 15) * 4;
            const float* Bp = B + (size_t)(k0 + r) * ldb + n0 + nn;
            #pragma unroll
            for (int u = 0; u < 4; u++) Bs[r][nn + u] = Bp[u];
        }
        __syncthreads();
        #pragma unroll
        for (int k = 0; k < 16; k++) {
            float a[4], b[4];
            #pragma unroll
            for (int u = 0; u < 4; u++) a[u] = As[k][ty * 4 + u];
            #pragma unroll
            for (int u = 0; u < 4; u++) b[u] = Bs[k][tx * 4 + u];
            #pragma unroll
            for (int x = 0; x < 4; x++)
                #pragma unroll
                for (int y = 0; y < 4; y++) acc[x][y] += a[x] * b[y];
        }
        __syncthreads();
    }
    #pragma unroll
    for (int x = 0; x < 4; x++) {
        int m = m0 + ty * 4 + x;
        #pragma unroll
        for (int y = 0; y < 4; y++) {
            int n = n0 + tx * 4 + y;
            float v = acc[x][y];
            if (bias) v += bias[n];
            C[(size_t)m * ldc + n] = v;
        }
    }
}

// ---------------- GCN helper kernels ----------------
__global__ void init_deg_kernel(float* deg, int n)
{
    int i = blockIdx.x * blockDim.x + threadIdx.x;
    if (i < n) deg[i] = 1.0f;
}

__global__ void accum_deg_kernel(const int* __restrict__ dst, int E, float* deg)
{
    int e = blockIdx.x * blockDim.x + threadIdx.x;
    if (e < E) atomicAdd(&deg[dst[e]], 1.0f);
}

// out[i, 0:256] = h[i]/deg[i] + b ;  out[i, 256:512] = 0
__global__ void gcn_self_kernel(float* __restrict__ out, const float* __restrict__ h,
                                const float* __restrict__ deg, const float* __restrict__ b,
                                int n)
{
    int idx = blockIdx.x * blockDim.x + threadIdx.x;
    if (idx >= n * DD) return;
    int i = idx >> 8, f = idx & 255;
    out[i * CAT + f]       = h[idx] / deg[i] + b[f];
    out[i * CAT + DD + f]  = 0.0f;
}

__global__ void gcn_edge_kernel(const int* __restrict__ src, const int* __restrict__ dst,
                                int E, const float* __restrict__ h,
                                const float* __restrict__ deg, float* __restrict__ out)
{
    int idx = blockIdx.x * blockDim.x + threadIdx.x;
    if (idx >= E * DD) return;
    int e = idx >> 8, f = idx & 255;
    int s = src[e], d = dst[e];
    float coef = rsqrtf(deg[s]) * rsqrtf(deg[d]);
    atomicAdd(&out[d * CAT + f], coef * h[s * DD + f]);
}

__global__ void relu_left_kernel(float* __restrict__ buf, int n)
{
    int idx = blockIdx.x * blockDim.x + threadIdx.x;
    if (idx >= n * DD) return;
    int i = idx >> 8, f = idx & 255;
    float v = buf[i * CAT + f];
    buf[i * CAT + f] = v > 0.0f ? v : 0.0f;
}

// ---------------- cross-matching kernels ----------------
__global__ void row_norms_kernel(const float* __restrict__ buf, int n, float* __restrict__ out)
{
    int i = blockIdx.x * (blockDim.x / 32) + (threadIdx.x >> 5);
    int lane = threadIdx.x & 31;
    if (i >= n) return;
    const float* p = buf + i * CAT;
    float s = 0.0f;
    for (int k = lane; k < DD; k += 32) { float v = p[k]; s += v * v; }
    #pragma unroll
    for (int o = 16; o; o >>= 1) s += __shfl_xor_sync(0xFFFFFFFFu, s, o);
    if (lane == 0) out[i] = fmaxf(sqrtf(s), 1e-8f);
}

__global__ void edge_cos_kernel(const int* __restrict__ qi, const int* __restrict__ di, int E,
                                const float* __restrict__ qbuf, const float* __restrict__ dbuf,
                                const float* __restrict__ qn, const float* __restrict__ dn,
                                float* __restrict__ cosw)
{
    int e = blockIdx.x * (blockDim.x / 32) + (threadIdx.x >> 5);
    int lane = threadIdx.x & 31;
    if (e >= E) return;
    int q = qi[e], d = di[e];
    const float* qp = qbuf + q * CAT;
    const float* dp = dbuf + d * CAT;
    float s = 0.0f;
    for (int k = lane; k < DD; k += 32) s += qp[k] * dp[k];
    #pragma unroll
    for (int o = 16; o; o >>= 1) s += __shfl_xor_sync(0xFFFFFFFFu, s, o);
    if (lane == 0) cosw[e] = s / (qn[q] * dn[d]);
}

// single-block global softmax over E entries, in-place cos -> weight
__global__ void softmax_kernel(float* __restrict__ cosw, int E)
{
    __shared__ float sred[256];
    int t = threadIdx.x;
    float m = -1e30f;
    for (int e = t; e < E; e += 256) m = fmaxf(m, cosw[e]);
    sred[t] = m; __syncthreads();
    for (int s = 128; s > 0; s >>= 1) {
        if (t < s) sred[t] = fmaxf(sred[t], sred[t + s]);
        __syncthreads();
    }
    float mx = sred[0];
    __syncthreads();
    float sum = 0.0f;
    for (int e = t; e < E; e += 256) sum += expf(cosw[e] - mx);
    sred[t] = sum; __syncthreads();
    for (int s = 128; s > 0; s >>= 1) {
        if (t < s) sred[t] += sred[t + s];
        __syncthreads();
    }
    float inv = 1.0f / sred[0];
    for (int e = t; e < E; e += 256) cosw[e] = expf(cosw[e] - mx) * inv;
}

__global__ void cross_agg_kernel(const int* __restrict__ qi, const int* __restrict__ di, int E,
                                 float* __restrict__ qbuf, float* __restrict__ dbuf,
                                 const float* __restrict__ w)
{
    int idx = blockIdx.x * blockDim.x + threadIdx.x;
    if (idx >= E * DD) return;
    int e = idx >> 8, f = idx & 255;
    float we = w[e];
    int q = qi[e], d = di[e];
    atomicAdd(&qbuf[q * CAT + DD + f], we * dbuf[d * CAT + f]);
    atomicAdd(&dbuf[d * CAT + DD + f], we * qbuf[q * CAT + f]);
}

// ---------------- all-pairs MLP kernel ----------------
// pred[i, j] = relu( relu( relu(Bq[i]+Bd[j]) @ w3 + b3 ) . w4 + b4 )
// grid: (8 j-tiles of 128, 128 i).  block: 256 threads (16x16), 8x8 reg tile.
__global__ void pair_mlp_kernel(const float* __restrict__ Bq, const float* __restrict__ Bd,
                                const float* __restrict__ w3, const float* __restrict__ b3,
                                const float* __restrict__ w4, const float* __restrict__ b4,
                                float* __restrict__ pred)
{
    __shared__ float Us[16][132];   // u[k][j]
    __shared__ float Ws[16][128];   // w3[k][n]
    __shared__ float Red[16][128];  // reduction buffer
    int i  = blockIdx.y;
    int j0 = blockIdx.x * 128;
    int t  = threadIdx.x;
    int tx = t & 15, ty = t >> 4;
    float acc[8][8] = {};
    for (int kc = 0; kc < DD; kc += 16) {
        {
            int j  = t >> 1;          // 0..127
            int kk = (t & 1) * 8;     // 0 or 8
            const float* bd = Bd + (size_t)(j0 + j) * DD + kc + kk;
            const float* bq = Bq + (size_t)i * DD + kc + kk;
            #pragma unroll
            for (int u = 0; u < 8; u++) {
                float v = bq[u] + bd[u];
                Us[kk + u][j] = v > 0.0f ? v : 0.0f;
            }
        }
        {
            int r  = t >> 4;          // 0..15
            int nn = (t & 15) * 8;
            const float* wp = w3 + (size_t)(kc + r) * 128 + nn;
            #pragma unroll
            for (int u = 0; u < 8; u++) Ws[r][nn + u] = wp[u];
        }
        __syncthreads();
        #pragma unroll
        for (int k = 0; k < 16; k++) {
            float a[8], b[8];
            #pragma unroll
            for (int u = 0; u < 8; u++) a[u] = Us[k][ty * 8 + u];
            #pragma unroll
            for (int u = 0; u < 8; u++) b[u] = Ws[k][tx * 8 + u];
            #pragma unroll
            for (int x = 0; x < 8; x++)
                #pragma unroll
                for (int y = 0; y < 8; y++) acc[x][y] += a[x] * b[y];
        }
        __syncthreads();
    }
    // epilogue: relu(+b3), dot with w4, reduce over the 128 hidden units
    float part[8];
    #pragma unroll
    for (int x = 0; x < 8; x++) {
        float s = 0.0f;
        #pragma unroll
        for (int y = 0; y < 8; y++) {
            int n = tx * 8 + y;
            float v = acc[x][y] + b3[n];
            v = v > 0.0f ? v : 0.0f;
            s += v * w4[n];
        }
        part[x] = s;
    }
    #pragma unroll
    for (int x = 0; x < 8; x++) Red[tx][ty * 8 + x] = part[x];
    __syncthreads();
    if (t < 128) {
        float s = 0.0f;
        #pragma unroll
        for (int q = 0; q < 16; q++) s += Red[q][t];
        s += b4[0];
        s = s > 0.0f ? s : 0.0f;
        pred[(size_t)i * ND + j0 + t] = s;
    }
}

__global__ void copy_kernel(const float* __restrict__ src, float* __restrict__ dst, int n)
{
    int i = blockIdx.x * blockDim.x + threadIdx.x;
    if (i < n) dst[i] = src[i];
}

// ---------------- host orchestration ----------------
static inline void run_gemm(const float* A, int lda, const float* B, int ldb,
                            float* C, int ldc, const float* bias, int M, int N, int K)
{
    dim3 grid(N / 64, M / 64);
    gemm_rt<<<grid, 256>>>(A, lda, B, ldb, C, ldc, bias, M, N, K);
}

static void run_gcn_layer(const float* X, int lda, int Din,
                          const float* W, const float* b,
                          const int* src, const int* dst, int E, int n,
                          float* h, float* deg, float* outbuf)
{
    run_gemm(X, lda, W, DD, h, DD, nullptr, n, DD, Din);
    init_deg_kernel<<<(n + 255) / 256, 256>>>(deg, n);
    accum_deg_kernel<<<(E + 255) / 256, 256>>>(dst, E, deg);
    gcn_self_kernel<<<n, 256>>>(outbuf, h, deg, b, n);
    gcn_edge_kernel<<<E, 256>>>(src, dst, E, h, deg, outbuf);
    relu_left_kernel<<<n, 256>>>(outbuf, n);
}

static void run_cross(const int* qi, const int* di, int EM,
                      float* qbuf, float* dbuf,
                      float* qnorm, float* dnorm, float* cosw)
{
    row_norms_kernel<<<(NQ + 7) / 8, 256>>>(qbuf, NQ, qnorm);
    row_norms_kernel<<<(ND + 7) / 8, 256>>>(dbuf, ND, dnorm);
    edge_cos_kernel<<<(EM + 7) / 8, 256>>>(qi, di, EM, qbuf, dbuf, qnorm, dnorm, cosw);
    softmax_kernel<<<1, 256>>>(cosw, EM);
    cross_agg_kernel<<<EM, 256>>>(qi, di, EM, qbuf, dbuf, cosw);
}

extern "C" void kernel_launch(void* const* d_in, const int* in_sizes, int n_in,
                              void* d_out, int out_size)
{
    const float* qfeat = (const float*)d_in[0];
    const float* dfeat = (const float*)d_in[1];
    const int*   qe    = (const int*)d_in[2];
    const int*   de    = (const int*)d_in[3];
    const int*   qi    = (const int*)d_in[4];
    const int*   di    = (const int*)d_in[5];
    const float* q_w0 = (const float*)d_in[6];
    const float* q_b0 = (const float*)d_in[7];
    const float* q_w1 = (const float*)d_in[8];
    const float* q_b1 = (const float*)d_in[9];
    const float* d_w0 = (const float*)d_in[10];
    const float* d_b0 = (const float*)d_in[11];
    const float* d_w1 = (const float*)d_in[12];
    const float* d_b1 = (const float*)d_in[13];
    const float* w1 = (const float*)d_in[14];
    const float* b1 = (const float*)d_in[15];
    const float* w2 = (const float*)d_in[16];
    const float* b2 = (const float*)d_in[17];
    const float* w3 = (const float*)d_in[18];
    const float* b3 = (const float*)d_in[19];
    const float* w4 = (const float*)d_in[20];
    const float* b4 = (const float*)d_in[21];

    int EQ = in_sizes[2] / 2;
    int ED = in_sizes[3] / 2;
    int EM = in_sizes[4];

    float *qA, *qB, *dA, *dB, *qh, *dh, *qdeg, *ddeg, *qnorm, *dnorm, *cosw, *Bqp, *Bdp;
    cudaGetSymbolAddress((void**)&qA, g_qA);
    cudaGetSymbolAddress((void**)&qB, g_qB);
    cudaGetSymbolAddress((void**)&dA, g_dA);
    cudaGetSymbolAddress((void**)&dB, g_dB);
    cudaGetSymbolAddress((void**)&qh, g_qh);
    cudaGetSymbolAddress((void**)&dh, g_dh);
    cudaGetSymbolAddress((void**)&qdeg, g_qdeg);
    cudaGetSymbolAddress((void**)&ddeg, g_ddeg);
    cudaGetSymbolAddress((void**)&qnorm, g_qnorm);
    cudaGetSymbolAddress((void**)&dnorm, g_dnorm);
    cudaGetSymbolAddress((void**)&cosw, g_cosw);
    cudaGetSymbolAddress((void**)&Bqp, g_Bq);
    cudaGetSymbolAddress((void**)&Bdp, g_Bd);

    float* out = (float*)d_out;

    // ---- layer 0 ----
    run_gcn_layer(qfeat, DD, DD, q_w0, q_b0, qe, qe + EQ, EQ, NQ, qh, qdeg, qB);
    run_gcn_layer(dfeat, DD, DD, d_w0, d_b0, de, de + ED, ED, ND, dh, ddeg, dB);
    run_cross(qi, di, EM, qB, dB, qnorm, dnorm, cosw);

    // ---- layer 1 ----
    run_gcn_layer(qB, CAT, CAT, q_w1, q_b1, qe, qe + EQ, EQ, NQ, qh, qdeg, qA);
    run_gcn_layer(dB, CAT, CAT, d_w1, d_b1, de, de + ED, ED, ND, dh, ddeg, dA);
    run_cross(qi, di, EM, qA, dA, qnorm, dnorm, cosw);

    // ---- final scoring ----
    // Aq = qf @ w1[0:512,:] + b1   (into qB, [128,512])
    run_gemm(qA, CAT, w1, CAT, qB, CAT, b1, NQ, CAT, CAT);
    // Ad = df @ w1[512:1024,:]     (into dB, [1024,512])
    run_gemm(dA, CAT, w1 + (size_t)CAT * CAT, CAT, dB, CAT, nullptr, ND, CAT, CAT);
    // Bq = Aq @ w2 + b2  [128,256]
    run_gemm(qB, CAT, w2, DD, Bqp, DD, b2, NQ, DD, CAT);
    // Bd = Ad @ w2       [1024,256]
    run_gemm(dB, CAT, w2, DD, Bdp, DD, nullptr, ND, DD, CAT);

    // per-pair MLP -> pred
    dim3 pg(ND / 128, NQ);
    pair_mlp_kernel<<<pg, 256>>>(Bqp, Bdp, w3, b3, w4, b4, out);

    // outputs: (pred, qf, df) flattened
    if (out_size >= NQ * ND + NQ * CAT + ND * CAT) {
        copy_kernel<<<(NQ * CAT + 255) / 256, 256>>>(qA, out + NQ * ND, NQ * CAT);
        copy_kernel<<<(ND * CAT + 255) / 256, 256>>>(dA, out + NQ * ND + NQ * CAT, ND * CAT);
    }
}

// round 3
// speedup vs baseline: 1.3123x; 1.3123x over previous
#include <cuda_runtime.h>
#include <cuda_bf16.h>
#include <cstdint>
#include <math.h>

#define NQ 128
#define ND 1024
#define DD 256
#define CAT 512

// ---------------- device scratch ----------------
__device__ float g_qA[NQ * CAT];
__device__ float g_qB[NQ * CAT];
__device__ float g_dA[ND * CAT];
__device__ float g_dB[ND * CAT];
__device__ float g_qh[NQ * DD];
__device__ float g_dh[ND * DD];
__device__ float g_qdeg[NQ];
__device__ float g_ddeg[ND];
__device__ float g_qnorm[NQ];
__device__ float g_dnorm[ND];
__device__ float g_cosw[8192];
__device__ float g_Bq[NQ * DD];
__device__ float g_Bd[ND * DD];
__device__ __align__(16) __nv_bfloat16 g_w3hi[128 * 256];  // w3^T hi part, [n][k]
__device__ __align__(16) __nv_bfloat16 g_w3lo[128 * 256];  // w3^T lo part, [n][k]

// ---------------- generic register-tiled GEMM ----------------
__global__ void gemm_rt(const float* __restrict__ A, int lda,
                        const float* __restrict__ B, int ldb,
                        float* __restrict__ C, int ldc,
                        const float* __restrict__ bias,
                        int M, int N, int K)
{
    __shared__ float As[16][65];
    __shared__ float Bs[16][65];
    int t  = threadIdx.x;
    int tx = t & 15, ty = t >> 4;
    int m0 = blockIdx.y * 64, n0 = blockIdx.x * 64;
    float acc[4][4] = {};
    for (int k0 = 0; k0 < K; k0 += 16) {
        {
            int r  = t >> 2;
            int kk = (t & 3) * 4;
            const float* Ap = A + (size_t)(m0 + r) * lda + k0 + kk;
            #pragma unroll
            for (int u = 0; u < 4; u++) As[kk + u][r] = Ap[u];
        }
        {
            int r  = t >> 4;
            int nn = (t & 15) * 4;
            const float* Bp = B + (size_t)(k0 + r) * ldb + n0 + nn;
            #pragma unroll
            for (int u = 0; u < 4; u++) Bs[r][nn + u] = Bp[u];
        }
        __syncthreads();
        #pragma unroll
        for (int k = 0; k < 16; k++) {
            float a[4], b[4];
            #pragma unroll
            for (int u = 0; u < 4; u++) a[u] = As[k][ty * 4 + u];
            #pragma unroll
            for (int u = 0; u < 4; u++) b[u] = Bs[k][tx * 4 + u];
            #pragma unroll
            for (int x = 0; x < 4; x++)
                #pragma unroll
                for (int y = 0; y < 4; y++) acc[x][y] += a[x] * b[y];
        }
        __syncthreads();
    }
    #pragma unroll
    for (int x = 0; x < 4; x++) {
        int m = m0 + ty * 4 + x;
        #pragma unroll
        for (int y = 0; y < 4; y++) {
            int n = n0 + tx * 4 + y;
            float v = acc[x][y];
            if (bias) v += bias[n];
            C[(size_t)m * ldc + n] = v;
        }
    }
}

// ---------------- GCN helper kernels ----------------
__global__ void init_deg_kernel(float* deg, int n)
{
    int i = blockIdx.x * blockDim.x + threadIdx.x;
    if (i < n) deg[i] = 1.0f;
}

__global__ void accum_deg_kernel(const int* __restrict__ dst, int E, float* deg)
{
    int e = blockIdx.x * blockDim.x + threadIdx.x;
    if (e < E) atomicAdd(&deg[dst[e]], 1.0f);
}

__global__ void gcn_self_kernel(float* __restrict__ out, const float* __restrict__ h,
                                const float* __restrict__ deg, const float* __restrict__ b,
                                int n)
{
    int idx = blockIdx.x * blockDim.x + threadIdx.x;
    if (idx >= n * DD) return;
    int i = idx >> 8, f = idx & 255;
    out[i * CAT + f]       = h[idx] / deg[i] + b[f];
    out[i * CAT + DD + f]  = 0.0f;
}

__global__ void gcn_edge_kernel(const int* __restrict__ src, const int* __restrict__ dst,
                                int E, const float* __restrict__ h,
                                const float* __restrict__ deg, float* __restrict__ out)
{
    int idx = blockIdx.x * blockDim.x + threadIdx.x;
    if (idx >= E * DD) return;
    int e = idx >> 8, f = idx & 255;
    int s = src[e], d = dst[e];
    float coef = rsqrtf(deg[s]) * rsqrtf(deg[d]);
    atomicAdd(&out[d * CAT + f], coef * h[s * DD + f]);
}

__global__ void relu_left_kernel(float* __restrict__ buf, int n)
{
    int idx = blockIdx.x * blockDim.x + threadIdx.x;
    if (idx >= n * DD) return;
    int i = idx >> 8, f = idx & 255;
    float v = buf[i * CAT + f];
    buf[i * CAT + f] = v > 0.0f ? v : 0.0f;
}

// ---------------- cross-matching kernels ----------------
__global__ void row_norms_kernel(const float* __restrict__ buf, int n, float* __restrict__ out)
{
    int i = blockIdx.x * (blockDim.x / 32) + (threadIdx.x >> 5);
    int lane = threadIdx.x & 31;
    if (i >= n) return;
    const float* p = buf + i * CAT;
    float s = 0.0f;
    for (int k = lane; k < DD; k += 32) { float v = p[k]; s += v * v; }
    #pragma unroll
    for (int o = 16; o; o >>= 1) s += __shfl_xor_sync(0xFFFFFFFFu, s, o);
    if (lane == 0) out[i] = fmaxf(sqrtf(s), 1e-8f);
}

__global__ void edge_cos_kernel(const int* __restrict__ qi, const int* __restrict__ di, int E,
                                const float* __restrict__ qbuf, const float* __restrict__ dbuf,
                                const float* __restrict__ qn, const float* __restrict__ dn,
                                float* __restrict__ cosw)
{
    int e = blockIdx.x * (blockDim.x / 32) + (threadIdx.x >> 5);
    int lane = threadIdx.x & 31;
    if (e >= E) return;
    int q = qi[e], d = di[e];
    const float* qp = qbuf + q * CAT;
    const float* dp = dbuf + d * CAT;
    float s = 0.0f;
    for (int k = lane; k < DD; k += 32) s += qp[k] * dp[k];
    #pragma unroll
    for (int o = 16; o; o >>= 1) s += __shfl_xor_sync(0xFFFFFFFFu, s, o);
    if (lane == 0) cosw[e] = s / (qn[q] * dn[d]);
}

__global__ void softmax_kernel(float* __restrict__ cosw, int E)
{
    __shared__ float sred[256];
    int t = threadIdx.x;
    float m = -1e30f;
    for (int e = t; e < E; e += 256) m = fmaxf(m, cosw[e]);
    sred[t] = m; __syncthreads();
    for (int s = 128; s > 0; s >>= 1) {
        if (t < s) sred[t] = fmaxf(sred[t], sred[t + s]);
        __syncthreads();
    }
    float mx = sred[0];
    __syncthreads();
    float sum = 0.0f;
    for (int e = t; e < E; e += 256) sum += expf(cosw[e] - mx);
    sred[t] = sum; __syncthreads();
    for (int s = 128; s > 0; s >>= 1) {
        if (t < s) sred[t] += sred[t + s];
        __syncthreads();
    }
    float inv = 1.0f / sred[0];
    for (int e = t; e < E; e += 256) cosw[e] = expf(cosw[e] - mx) * inv;
}

__global__ void cross_agg_kernel(const int* __restrict__ qi, const int* __restrict__ di, int E,
                                 float* __restrict__ qbuf, float* __restrict__ dbuf,
                                 const float* __restrict__ w)
{
    int idx = blockIdx.x * blockDim.x + threadIdx.x;
    if (idx >= E * DD) return;
    int e = idx >> 8, f = idx & 255;
    float we = w[e];
    int q = qi[e], d = di[e];
    atomicAdd(&qbuf[q * CAT + DD + f], we * dbuf[d * CAT + f]);
    atomicAdd(&dbuf[d * CAT + DD + f], we * qbuf[q * CAT + f]);
}

// ---------------- w3 transpose + bf16 split-pack ----------------
// w3hi/w3lo: [n][k] row-major, n=0..127, k=0..255.  w3 = hi + lo to ~16-bit mantissa.
__global__ void pack_w3_kernel(const float* __restrict__ w3,
                               __nv_bfloat16* __restrict__ hi, __nv_bfloat16* __restrict__ lo)
{
    int idx = blockIdx.x * blockDim.x + threadIdx.x;
    if (idx >= 128 * 256) return;
    int n = idx >> 8, k = idx & 255;
    float v = w3[(size_t)k * 128 + n];
    __nv_bfloat16 h = __float2bfloat16(v);
    float r = v - __bfloat162float(h);
    hi[idx] = h;
    lo[idx] = __float2bfloat16(r);
}

// ---------------- HMMA pair-MLP kernel ----------------
// pred[i, j] = relu( relu( relu(Bq[i]+Bd[j]) @ w3 + b3 ) . w4 + b4 )
// mma.sync.m16n8k16 bf16, 3-pass split precision (Ahi*Bhi + Alo*Bhi + Ahi*Blo).
// CTA: 64-row j-tile x 8-i group. block 512 (16 warps: warp_m=wid&3, warp_n=wid>>2).
#define SM_BQ   0
#define SM_B3   1024
#define SM_W4   1536
#define SM_RED  2048
#define SM_BD   4096
#define BD_STR  1032                 // 258 words; (258/2) mod 16 odd -> conflict-free frags
#define SM_W3H  (SM_BD + 64 * BD_STR)        // 70144
#define W3_STR  528                  // 132 words; 132 mod 32 = 4 -> conflict-free frags
#define SM_W3L  (SM_W3H + 128 * W3_STR)      // 137728
#define SM_PAIR_TOTAL (SM_W3L + 128 * W3_STR)  // 205312

__device__ __forceinline__ void mma_bf16(float c[4],
                                         uint32_t a0, uint32_t a1, uint32_t a2, uint32_t a3,
                                         uint32_t b0, uint32_t b1)
{
    asm volatile("mma.sync.aligned.m16n8k16.row.col.f32.bf16.bf16.f32 "
                 "{%0,%1,%2,%3}, {%4,%5,%6,%7}, {%8,%9}, {%0,%1,%2,%3};"
                 : "+f"(c[0]), "+f"(c[1]), "+f"(c[2]), "+f"(c[3])
                 : "r"(a0), "r"(a1), "r"(a2), "r"(a3), "r"(b0), "r"(b1));
}

// pack two f32 (v0=low bf16, v1=high bf16) and produce the residual pack too
__device__ __forceinline__ void split_pack(float v0, float v1, uint32_t& hi, uint32_t& lo)
{
    asm("cvt.rn.bf16x2.f32 %0, %1, %2;" : "=r"(hi) : "f"(v1), "f"(v0));
    float h0 = __uint_as_float(hi << 16);
    float h1 = __uint_as_float(hi & 0xffff0000u);
    float r0 = v0 - h0, r1 = v1 - h1;
    asm("cvt.rn.bf16x2.f32 %0, %1, %2;" : "=r"(lo) : "f"(r1), "f"(r0));
}

__global__ void __launch_bounds__(512, 1)
pair_hmma_kernel(const float* __restrict__ Bq, const float* __restrict__ Bd,
                 const __nv_bfloat16* __restrict__ w3hi, const __nv_bfloat16* __restrict__ w3lo,
                 const float* __restrict__ b3, const float* __restrict__ w4,
                 const float* __restrict__ b4, float* __restrict__ pred)
{
    extern __shared__ char smem[];
    const int t = threadIdx.x, lane = t & 31, wid = t >> 5;
    const int warp_m = wid & 3, warp_n = wid >> 2;
    const int j0 = blockIdx.x * 64;
    const int i0 = blockIdx.y * 8;

    // fill Bd tile [64 x 256 f32], stride 1032B
    for (int v = t; v < 64 * 128; v += 512) {
        int row = v >> 7, c = v & 127;
        *(float2*)(smem + SM_BD + row * BD_STR + c * 8) =
            ((const float2*)(Bd + (size_t)(j0 + row) * DD))[c];
    }
    // fill w3 hi/lo [128 x 256 bf16], stride 528B
    for (int v = t; v < 128 * 32; v += 512) {
        int row = v >> 5, c = v & 31;
        *(uint4*)(smem + SM_W3H + row * W3_STR + c * 16) =
            ((const uint4*)(w3hi + (size_t)row * DD))[c];
        *(uint4*)(smem + SM_W3L + row * W3_STR + c * 16) =
            ((const uint4*)(w3lo + (size_t)row * DD))[c];
    }
    if (t < 32) ((uint4*)(smem + SM_B3))[t] = ((const uint4*)b3)[t];
    else if (t < 64) ((uint4*)(smem + SM_W4))[t - 32] = ((const uint4*)w4)[t - 32];
    const float b4v = b4[0];

    const float* b3s = (const float*)(smem + SM_B3);
    const float* w4s = (const float*)(smem + SM_W4);
    float* red = (float*)(smem + SM_RED);

    const int r_lo = warp_m * 16 + (lane >> 2);
    const char* bd_lo = smem + SM_BD + r_lo * BD_STR;
    const char* bd_hi = bd_lo + 8 * BD_STR;
    const int kq = (lane & 3) * 2;
    const int nrow = warp_n * 32 + (lane >> 2);   // + nt*8

    for (int il = 0; il < 8; il++) {
        __syncthreads();
        if (t < 64) ((uint4*)(smem + SM_BQ))[t] = ((const uint4*)(Bq + (size_t)(i0 + il) * DD))[t];
        __syncthreads();

        float c[4][4];
        #pragma unroll
        for (int nt = 0; nt < 4; nt++)
            #pragma unroll
            for (int u = 0; u < 4; u++) c[nt][u] = 0.0f;

        #pragma unroll
        for (int ks = 0; ks < 16; ks++) {
            const int kb = ks * 16 + kq;
            float2 q0 = *(const float2*)(smem + SM_BQ + kb * 4);
            float2 q1 = *(const float2*)(smem + SM_BQ + (kb + 8) * 4);
            uint32_t ah[4], al[4];
            {
                float2 d = *(const float2*)(bd_lo + kb * 4);
                split_pack(fmaxf(d.x + q0.x, 0.0f), fmaxf(d.y + q0.y, 0.0f), ah[0], al[0]);
            }
            {
                float2 d = *(const float2*)(bd_hi + kb * 4);
                split_pack(fmaxf(d.x + q0.x, 0.0f), fmaxf(d.y + q0.y, 0.0f), ah[1], al[1]);
            }
            {
                float2 d = *(const float2*)(bd_lo + (kb + 8) * 4);
                split_pack(fmaxf(d.x + q1.x, 0.0f), fmaxf(d.y + q1.y, 0.0f), ah[2], al[2]);
            }
            {
                float2 d = *(const float2*)(bd_hi + (kb + 8) * 4);
                split_pack(fmaxf(d.x + q1.x, 0.0f), fmaxf(d.y + q1.y, 0.0f), ah[3], al[3]);
            }
            #pragma unroll
            for (int nt = 0; nt < 4; nt++) {
                const int roff = (nrow + nt * 8) * W3_STR + kb * 2;
                uint32_t bh0 = *(const uint32_t*)(smem + SM_W3H + roff);
                uint32_t bh1 = *(const uint32_t*)(smem + SM_W3H + roff + 16);
                uint32_t bl0 = *(const uint32_t*)(smem + SM_W3L + roff);
                uint32_t bl1 = *(const uint32_t*)(smem + SM_W3L + roff + 16);
                mma_bf16(c[nt], ah[0], ah[1], ah[2], ah[3], bh0, bh1);
                mma_bf16(c[nt], al[0], al[1], al[2], al[3], bh0, bh1);
                mma_bf16(c[nt], ah[0], ah[1], ah[2], ah[3], bl0, bl1);
            }
        }

        // epilogue: relu(+b3) . w4
        float s_lo = 0.0f, s_hi = 0.0f;
        #pragma unroll
        for (int nt = 0; nt < 4; nt++) {
            int n0 = warp_n * 32 + nt * 8 + (lane & 3) * 2;
            float b30 = b3s[n0], b31 = b3s[n0 + 1];
            float w40 = w4s[n0], w41 = w4s[n0 + 1];
            s_lo += fmaxf(c[nt][0] + b30, 0.0f) * w40 + fmaxf(c[nt][1] + b31, 0.0f) * w41;
            s_hi += fmaxf(c[nt][2] + b30, 0.0f) * w40 + fmaxf(c[nt][3] + b31, 0.0f) * w41;
        }
        s_lo += __shfl_xor_sync(0xFFFFFFFFu, s_lo, 1);
        s_lo += __shfl_xor_sync(0xFFFFFFFFu, s_lo, 2);
        s_hi += __shfl_xor_sync(0xFFFFFFFFu, s_hi, 1);
        s_hi += __shfl_xor_sync(0xFFFFFFFFu, s_hi, 2);
        if ((lane & 3) == 0) {
            red[r_lo * 4 + warp_n] = s_lo;
            red[(r_lo + 8) * 4 + warp_n] = s_hi;
        }
        __syncthreads();
        if (t < 64) {
            float v = red[t * 4] + red[t * 4 + 1] + red[t * 4 + 2] + red[t * 4 + 3] + b4v;
            v = v > 0.0f ? v : 0.0f;
            pred[(size_t)(i0 + il) * ND + j0 + t] = v;
        }
    }
}

__global__ void copy_kernel(const float* __restrict__ src, float* __restrict__ dst, int n)
{
    int i = blockIdx.x * blockDim.x + threadIdx.x;
    if (i < n) dst[i] = src[i];
}

// ---------------- host orchestration ----------------
static inline void run_gemm(const float* A, int lda, const float* B, int ldb,
                            float* C, int ldc, const float* bias, int M, int N, int K)
{
    dim3 grid(N / 64, M / 64);
    gemm_rt<<<grid, 256>>>(A, lda, B, ldb, C, ldc, bias, M, N, K);
}

static void run_gcn_layer(const float* X, int lda, int Din,
                          const float* W, const float* b,
                          const int* src, const int* dst, int E, int n,
                          float* h, float* deg, float* outbuf)
{
    run_gemm(X, lda, W, DD, h, DD, nullptr, n, DD, Din);
    init_deg_kernel<<<(n + 255) / 256, 256>>>(deg, n);
    accum_deg_kernel<<<(E + 255) / 256, 256>>>(dst, E, deg);
    gcn_self_kernel<<<n, 256>>>(outbuf, h, deg, b, n);
    gcn_edge_kernel<<<E, 256>>>(src, dst, E, h, deg, outbuf);
    relu_left_kernel<<<n, 256>>>(outbuf, n);
}

static void run_cross(const int* qi, const int* di, int EM,
                      float* qbuf, float* dbuf,
                      float* qnorm, float* dnorm, float* cosw)
{
    row_norms_kernel<<<(NQ + 7) / 8, 256>>>(qbuf, NQ, qnorm);
    row_norms_kernel<<<(ND + 7) / 8, 256>>>(dbuf, ND, dnorm);
    edge_cos_kernel<<<(EM + 7) / 8, 256>>>(qi, di, EM, qbuf, dbuf, qnorm, dnorm, cosw);
    softmax_kernel<<<1, 256>>>(cosw, EM);
    cross_agg_kernel<<<EM, 256>>>(qi, di, EM, qbuf, dbuf, cosw);
}

extern "C" void kernel_launch(void* const* d_in, const int* in_sizes, int n_in,
                              void* d_out, int out_size)
{
    const float* qfeat = (const float*)d_in[0];
    const float* dfeat = (const float*)d_in[1];
    const int*   qe    = (const int*)d_in[2];
    const int*   de    = (const int*)d_in[3];
    const int*   qi    = (const int*)d_in[4];
    const int*   di    = (const int*)d_in[5];
    const float* q_w0 = (const float*)d_in[6];
    const float* q_b0 = (const float*)d_in[7];
    const float* q_w1 = (const float*)d_in[8];
    const float* q_b1 = (const float*)d_in[9];
    const float* d_w0 = (const float*)d_in[10];
    const float* d_b0 = (const float*)d_in[11];
    const float* d_w1 = (const float*)d_in[12];
    const float* d_b1 = (const float*)d_in[13];
    const float* w1 = (const float*)d_in[14];
    const float* b1 = (const float*)d_in[15];
    const float* w2 = (const float*)d_in[16];
    const float* b2 = (const float*)d_in[17];
    const float* w3 = (const float*)d_in[18];
    const float* b3 = (const float*)d_in[19];
    const float* w4 = (const float*)d_in[20];
    const float* b4 = (const float*)d_in[21];

    int EQ = in_sizes[2] / 2;
    int ED = in_sizes[3] / 2;
    int EM = in_sizes[4];

    float *qA, *qB, *dA, *dB, *qh, *dh, *qdeg, *ddeg, *qnorm, *dnorm, *cosw, *Bqp, *Bdp;
    __nv_bfloat16 *w3hi, *w3lo;
    cudaGetSymbolAddress((void**)&qA, g_qA);
    cudaGetSymbolAddress((void**)&qB, g_qB);
    cudaGetSymbolAddress((void**)&dA, g_dA);
    cudaGetSymbolAddress((void**)&dB, g_dB);
    cudaGetSymbolAddress((void**)&qh, g_qh);
    cudaGetSymbolAddress((void**)&dh, g_dh);
    cudaGetSymbolAddress((void**)&qdeg, g_qdeg);
    cudaGetSymbolAddress((void**)&ddeg, g_ddeg);
    cudaGetSymbolAddress((void**)&qnorm, g_qnorm);
    cudaGetSymbolAddress((void**)&dnorm, g_dnorm);
    cudaGetSymbolAddress((void**)&cosw, g_cosw);
    cudaGetSymbolAddress((void**)&Bqp, g_Bq);
    cudaGetSymbolAddress((void**)&Bdp, g_Bd);
    cudaGetSymbolAddress((void**)&w3hi, g_w3hi);
    cudaGetSymbolAddress((void**)&w3lo, g_w3lo);

    float* out = (float*)d_out;

    cudaFuncSetAttribute(pair_hmma_kernel, cudaFuncAttributeMaxDynamicSharedMemorySize,
                         SM_PAIR_TOTAL);

    // pack w3 early (independent of everything else)
    pack_w3_kernel<<<128, 256>>>(w3, w3hi, w3lo);

    // ---- layer 0 ----
    run_gcn_layer(qfeat, DD, DD, q_w0, q_b0, qe, qe + EQ, EQ, NQ, qh, qdeg, qB);
    run_gcn_layer(dfeat, DD, DD, d_w0, d_b0, de, de + ED, ED, ND, dh, ddeg, dB);
    run_cross(qi, di, EM, qB, dB, qnorm, dnorm, cosw);

    // ---- layer 1 ----
    run_gcn_layer(qB, CAT, CAT, q_w1, q_b1, qe, qe + EQ, EQ, NQ, qh, qdeg, qA);
    run_gcn_layer(dB, CAT, CAT, d_w1, d_b1, de, de + ED, ED, ND, dh, ddeg, dA);
    run_cross(qi, di, EM, qA, dA, qnorm, dnorm, cosw);

    // ---- final scoring (w1/w2 folded: no nonlinearity between them) ----
    run_gemm(qA, CAT, w1, CAT, qB, CAT, b1, NQ, CAT, CAT);
    run_gemm(dA, CAT, w1 + (size_t)CAT * CAT, CAT, dB, CAT, nullptr, ND, CAT, CAT);
    run_gemm(qB, CAT, w2, DD, Bqp, DD, b2, NQ, DD, CAT);
    run_gemm(dB, CAT, w2, DD, Bdp, DD, nullptr, ND, DD, CAT);

    // tensor-core per-pair MLP -> pred
    dim3 pg(ND / 64, NQ / 8);
    pair_hmma_kernel<<<pg, 512, SM_PAIR_TOTAL>>>(Bqp, Bdp, w3hi, w3lo, b3, w4, b4, out);

    // outputs: (pred, qf, df) flattened
    if (out_size >= NQ * ND + NQ * CAT + ND * CAT) {
        copy_kernel<<<(NQ * CAT + 255) / 256, 256>>>(qA, out + NQ * ND, NQ * CAT);
        copy_kernel<<<(ND * CAT + 255) / 256, 256>>>(dA, out + NQ * ND + NQ * CAT, ND * CAT);
    }
}

// round 4
// speedup vs baseline: 1.9424x; 1.4801x over previous
#include <cuda_runtime.h>
#include <cuda_bf16.h>
#include <cstdint>
#include <math.h>

#define NQ 128
#define ND 1024
#define DD 256
#define CAT 512

// ---------------- device scratch ----------------
__device__ float g_qh[NQ * DD];
__device__ float g_dh[ND * DD];
__device__ float g_qB[NQ * CAT];
__device__ float g_dB[ND * CAT];
__device__ float g_qdeg[NQ];
__device__ float g_ddeg[ND];
__device__ float g_cosw[8192];
__device__ float g_Bq[NQ * DD];
__device__ float g_Bd[ND * DD];

// packed weights: [N][K] bf16, hi and lo parts
#define OFF_QW0 0
#define OFF_DW0 65536
#define OFF_QW1 131072
#define OFF_DW1 262144
#define OFF_W1T 393216
#define OFF_W1B 655360
#define OFF_W2  917504
#define OFF_W3  1048576
#define WPACK_TOTAL 1081344
__device__ __align__(16) __nv_bfloat16 g_wh[WPACK_TOTAL];
__device__ __align__(16) __nv_bfloat16 g_wl[WPACK_TOTAL];

// ---------------- shared helpers ----------------
__device__ __forceinline__ void mma_bf16(float c[4],
                                         uint32_t a0, uint32_t a1, uint32_t a2, uint32_t a3,
                                         uint32_t b0, uint32_t b1)
{
    asm volatile("mma.sync.aligned.m16n8k16.row.col.f32.bf16.bf16.f32 "
                 "{%0,%1,%2,%3}, {%4,%5,%6,%7}, {%8,%9}, {%0,%1,%2,%3};"
                 : "+f"(c[0]), "+f"(c[1]), "+f"(c[2]), "+f"(c[3])
                 : "r"(a0), "r"(a1), "r"(a2), "r"(a3), "r"(b0), "r"(b1));
}

__device__ __forceinline__ void split_pack(float v0, float v1, uint32_t& hi, uint32_t& lo)
{
    asm("cvt.rn.bf16x2.f32 %0, %1, %2;" : "=r"(hi) : "f"(v1), "f"(v0));
    float h0 = __uint_as_float(hi << 16);
    float h1 = __uint_as_float(hi & 0xffff0000u);
    float r0 = v0 - h0, r1 = v1 - h1;
    asm("cvt.rn.bf16x2.f32 %0, %1, %2;" : "=r"(lo) : "f"(r1), "f"(r0));
}

// ---------------- weight pack: transpose + bf16 split ----------------
struct PackJob { const float* src; int K, N, ld; int64_t off; };
struct PackArgs { PackJob j[8]; };

__global__ void pack_kernel(PackArgs pa, __nv_bfloat16* __restrict__ wh,
                            __nv_bfloat16* __restrict__ wl)
{
    __shared__ float tile[32][33];
    const PackJob jb = pa.j[blockIdx.y];
    int ntilesK = jb.K >> 5;
    int ntiles = ntilesK * (jb.N >> 5);
    if ((int)blockIdx.x >= ntiles) return;
    int kt = blockIdx.x % ntilesK, nt = blockIdx.x / ntilesK;
    int tx = threadIdx.x & 31, ty = threadIdx.x >> 5;
    #pragma unroll
    for (int p = 0; p < 4; p++) {
        int row = ty + p * 8;
        tile[row][tx] = jb.src[(size_t)(kt * 32 + row) * jb.ld + nt * 32 + tx];
    }
    __syncthreads();
    #pragma unroll
    for (int p = 0; p < 4; p++) {
        int row = ty + p * 8;                       // n within tile
        float v = tile[tx][row];
        __nv_bfloat16 h = __float2bfloat16(v);
        float r = v - __bfloat162float(h);
        size_t o = jb.off + (size_t)(nt * 32 + row) * jb.K + kt * 32 + tx;
        wh[o] = h;
        wl[o] = __float2bfloat16(r);
    }
}

// ---------------- HMMA split-bf16 GEMM ----------------
// C[M,N] = A[M,K](f32) @ B, B given pre-split transposed: BT[n][k] bf16 hi/lo.
// CTA tile 128x64, 8 warps (4 m x 2 n), K-chunk 64.
struct GemmJob {
    const float* A;
    const __nv_bfloat16* Bh;
    const __nv_bfloat16* Bl;
    float* C;
    const float* bias;
    int M, N, K, lda, ldc;
};

#define HG_A    0
#define HG_ASTR 288
#define HG_BH   36864
#define HG_BL   46080
#define HG_BSTR 144
#define HG_SMEM 55296

__global__ void __launch_bounds__(256, 2)
hgemm_kernel(GemmJob j0, GemmJob j1)
{
    GemmJob jb = (blockIdx.z == 0) ? j0 : j1;
    const int n0 = blockIdx.x * 64;
    const int m0 = blockIdx.y * 128;
    if (n0 >= jb.N || m0 >= jb.M) return;
    extern __shared__ char sm[];
    const int t = threadIdx.x, lane = t & 31, wid = t >> 5;
    const int warp_m = wid & 3, warp_n = wid >> 2;
    const int qr = lane >> 2, qk = (lane & 3) * 2;
    float acc[2][4][4] = {};

    for (int kc = 0; kc < jb.K; kc += 64) {
        __syncthreads();
        {   // A chunk fill: 128 rows x 64 cols f32
            int row = t >> 1, half = t & 1;
            const float4* src = (const float4*)(jb.A + (size_t)(m0 + row) * jb.lda + kc + half * 32);
            float4* dst = (float4*)(sm + HG_A + row * HG_ASTR + half * 128);
            #pragma unroll
            for (int i = 0; i < 8; i++) dst[i] = src[i];
        }
        #pragma unroll
        for (int p = 0; p < 2; p++) {   // B chunk fill: 64 n-rows x 64 k bf16 (hi+lo)
            int idx = t + p * 256;
            int row = idx >> 3, c = idx & 7;
            size_t go = (size_t)(n0 + row) * jb.K + kc + c * 8;
            *(uint4*)(sm + HG_BH + row * HG_BSTR + c * 16) = *(const uint4*)(jb.Bh + go);
            *(uint4*)(sm + HG_BL + row * HG_BSTR + c * 16) = *(const uint4*)(jb.Bl + go);
        }
        __syncthreads();
        #pragma unroll
        for (int kk = 0; kk < 64; kk += 16) {
            uint32_t bh[4][2], bl[4][2];
            #pragma unroll
            for (int f = 0; f < 4; f++) {
                int n = warp_n * 32 + f * 8 + qr;
                const char* bp = sm + n * HG_BSTR + (kk + qk) * 2;
                bh[f][0] = *(const uint32_t*)(bp + HG_BH);
                bh[f][1] = *(const uint32_t*)(bp + HG_BH + 16);
                bl[f][0] = *(const uint32_t*)(bp + HG_BL);
                bl[f][1] = *(const uint32_t*)(bp + HG_BL + 16);
            }
            #pragma unroll
            for (int s = 0; s < 2; s++) {
                int r = warp_m * 32 + s * 16 + qr;
                const char* ap = sm + HG_A + r * HG_ASTR + (kk + qk) * 4;
                float2 a0 = *(const float2*)ap;
                float2 a1 = *(const float2*)(ap + 8 * HG_ASTR);
                float2 a2 = *(const float2*)(ap + 32);
                float2 a3 = *(const float2*)(ap + 8 * HG_ASTR + 32);
                uint32_t ah[4], al[4];
                split_pack(a0.x, a0.y, ah[0], al[0]);
                split_pack(a1.x, a1.y, ah[1], al[1]);
                split_pack(a2.x, a2.y, ah[2], al[2]);
                split_pack(a3.x, a3.y, ah[3], al[3]);
                #pragma unroll
                for (int f = 0; f < 4; f++) {
                    mma_bf16(acc[s][f], ah[0], ah[1], ah[2], ah[3], bh[f][0], bh[f][1]);
                    mma_bf16(acc[s][f], al[0], al[1], al[2], al[3], bh[f][0], bh[f][1]);
                    mma_bf16(acc[s][f], ah[0], ah[1], ah[2], ah[3], bl[f][0], bl[f][1]);
                }
            }
        }
    }
    #pragma unroll
    for (int s = 0; s < 2; s++) {
        int r = m0 + warp_m * 32 + s * 16 + qr;
        #pragma unroll
        for (int f = 0; f < 4; f++) {
            int n = n0 + warp_n * 32 + f * 8 + qk;
            float bs0 = jb.bias ? jb.bias[n] : 0.0f;
            float bs1 = jb.bias ? jb.bias[n + 1] : 0.0f;
            float2 v0 = { acc[s][f][0] + bs0, acc[s][f][1] + bs1 };
            float2 v1 = { acc[s][f][2] + bs0, acc[s][f][3] + bs1 };
            *(float2*)(jb.C + (size_t)r * jb.ldc + n) = v0;
            *(float2*)(jb.C + (size_t)(r + 8) * jb.ldc + n) = v1;
        }
    }
}

// ---------------- fused graph kernels ----------------
__global__ void deg_init_kernel(float* qdeg, float* ddeg)
{
    int i = blockIdx.x * blockDim.x + threadIdx.x;
    if (i < NQ) qdeg[i] = 1.0f;
    else if (i < NQ + ND) ddeg[i - NQ] = 1.0f;
}

__global__ void deg_acc_kernel(const int* __restrict__ qdst, int EQ,
                               const int* __restrict__ ddst, int ED,
                               float* qdeg, float* ddeg)
{
    int e = blockIdx.x * blockDim.x + threadIdx.x;
    if (e < EQ) atomicAdd(&qdeg[qdst[e]], 1.0f);
    else if (e < EQ + ED) atomicAdd(&ddeg[ddst[e - EQ]], 1.0f);
}

// out[i,0:256] = h[i]/deg[i] + b ; out[i,256:512] = 0   (q and d fused, float4)
__global__ void self_fused_kernel(const float* __restrict__ qh, const float* __restrict__ dh,
                                  const float* __restrict__ qdeg, const float* __restrict__ ddeg,
                                  const float* __restrict__ qb, const float* __restrict__ db,
                                  float* __restrict__ qout, float* __restrict__ dout)
{
    const float4 z = {0.f, 0.f, 0.f, 0.f};
    int v = blockIdx.x * blockDim.x + threadIdx.x;
    if (v < NQ * 64) {
        int i = v >> 6, c = v & 63;
        float4 h = ((const float4*)qh)[i * 64 + c];
        float inv = 1.0f / qdeg[i];
        float4 b = ((const float4*)qb)[c];
        float4 o = { h.x * inv + b.x, h.y * inv + b.y, h.z * inv + b.z, h.w * inv + b.w };
        ((float4*)qout)[i * 128 + c] = o;
        ((float4*)qout)[i * 128 + 64 + c] = z;
    } else if (v < (NQ + ND) * 64) {
        v -= NQ * 64;
        int i = v >> 6, c = v & 63;
        float4 h = ((const float4*)dh)[i * 64 + c];
        float inv = 1.0f / ddeg[i];
        float4 b = ((const float4*)db)[c];
        float4 o = { h.x * inv + b.x, h.y * inv + b.y, h.z * inv + b.z, h.w * inv + b.w };
        ((float4*)dout)[i * 128 + c] = o;
        ((float4*)dout)[i * 128 + 64 + c] = z;
    }
}

__global__ void edge_fused_kernel(const int* __restrict__ qsrc, const int* __restrict__ qdst, int EQ,
                                  const int* __restrict__ dsrc, const int* __restrict__ ddst, int ED,
                                  const float* __restrict__ qh, const float* __restrict__ dh,
                                  const float* __restrict__ qdeg, const float* __restrict__ ddeg,
                                  float* __restrict__ qout, float* __restrict__ dout)
{
    int v = blockIdx.x * blockDim.x + threadIdx.x;
    if (v < EQ * 64) {
        int e = v >> 6, c = v & 63;
        int s = qsrc[e], d = qdst[e];
        float coef = rsqrtf(qdeg[s]) * rsqrtf(qdeg[d]);
        float4 h = ((const float4*)qh)[s * 64 + c];
        float* o = qout + d * CAT + c * 4;
        atomicAdd(o + 0, coef * h.x);
        atomicAdd(o + 1, coef * h.y);
        atomicAdd(o + 2, coef * h.z);
        atomicAdd(o + 3, coef * h.w);
    } else if (v < (EQ + ED) * 64) {
        v -= EQ * 64;
        int e = v >> 6, c = v & 63;
        int s = dsrc[e], d = ddst[e];
        float coef = rsqrtf(ddeg[s]) * rsqrtf(ddeg[d]);
        float4 h = ((const float4*)dh)[s * 64 + c];
        float* o = dout + d * CAT + c * 4;
        atomicAdd(o + 0, coef * h.x);
        atomicAdd(o + 1, coef * h.y);
        atomicAdd(o + 2, coef * h.z);
        atomicAdd(o + 3, coef * h.w);
    }
}

__global__ void relu_fused_kernel(float* __restrict__ qout, float* __restrict__ dout)
{
    int v = blockIdx.x * blockDim.x + threadIdx.x;
    float4* p;
    if (v < NQ * 64) p = (float4*)qout + (v >> 6) * 128 + (v & 63);
    else if (v < (NQ + ND) * 64) { v -= NQ * 64; p = (float4*)dout + (v >> 6) * 128 + (v & 63); }
    else return;
    float4 x = *p;
    x.x = fmaxf(x.x, 0.f); x.y = fmaxf(x.y, 0.f);
    x.z = fmaxf(x.z, 0.f); x.w = fmaxf(x.w, 0.f);
    *p = x;
}

// cos with inline norms: warp per edge
__global__ void cos_norm_kernel(const int* __restrict__ qi, const int* __restrict__ di, int E,
                                const float* __restrict__ qbuf, const float* __restrict__ dbuf,
                                float* __restrict__ cosw)
{
    int e = blockIdx.x * (blockDim.x >> 5) + (threadIdx.x >> 5);
    int lane = threadIdx.x & 31;
    if (e >= E) return;
    const float* qp = qbuf + qi[e] * CAT;
    const float* dp = dbuf + di[e] * CAT;
    float qq = 0.f, dd = 0.f, qd = 0.f;
    for (int k = lane; k < DD; k += 32) {
        float a = qp[k], b = dp[k];
        qq += a * a; dd += b * b; qd += a * b;
    }
    #pragma unroll
    for (int o = 16; o; o >>= 1) {
        qq += __shfl_xor_sync(0xFFFFFFFFu, qq, o);
        dd += __shfl_xor_sync(0xFFFFFFFFu, dd, o);
        qd += __shfl_xor_sync(0xFFFFFFFFu, qd, o);
    }
    if (lane == 0)
        cosw[e] = qd / (fmaxf(sqrtf(qq), 1e-8f) * fmaxf(sqrtf(dd), 1e-8f));
}

__global__ void softmax_kernel(float* __restrict__ cosw, int E)
{
    __shared__ float red[1024];
    int t = threadIdx.x;
    float m = -1e30f;
    for (int e = t; e < E; e += 1024) m = fmaxf(m, cosw[e]);
    red[t] = m; __syncthreads();
    for (int s = 512; s; s >>= 1) { if (t < s) red[t] = fmaxf(red[t], red[t + s]); __syncthreads(); }
    float mx = red[0]; __syncthreads();
    float sum = 0.f;
    for (int e = t; e < E; e += 1024) sum += expf(cosw[e] - mx);
    red[t] = sum; __syncthreads();
    for (int s = 512; s; s >>= 1) { if (t < s) red[t] += red[t + s]; __syncthreads(); }
    float inv = 1.0f / red[0];
    for (int e = t; e < E; e += 1024) cosw[e] = expf(cosw[e] - mx) * inv;
}

__global__ void cross_agg_kernel(const int* __restrict__ qi, const int* __restrict__ di, int E,
                                 float* __restrict__ qbuf, float* __restrict__ dbuf,
                                 const float* __restrict__ w)
{
    int v = blockIdx.x * blockDim.x + threadIdx.x;
    if (v >= E * 64) return;
    int e = v >> 6, c = v & 63;
    float we = w[e];
    int q = qi[e], d = di[e];
    float4 dv = ((const float4*)dbuf)[d * 128 + c];
    float4 qv = ((const float4*)qbuf)[q * 128 + c];
    float* qa = qbuf + q * CAT + DD + c * 4;
    float* da = dbuf + d * CAT + DD + c * 4;
    atomicAdd(qa + 0, we * dv.x);
    atomicAdd(qa + 1, we * dv.y);
    atomicAdd(qa + 2, we * dv.z);
    atomicAdd(qa + 3, we * dv.w);
    atomicAdd(da + 0, we * qv.x);
    atomicAdd(da + 1, we * qv.y);
    atomicAdd(da + 2, we * qv.z);
    atomicAdd(da + 3, we * qv.w);
}

// ---------------- HMMA pair-MLP kernel (unchanged from R3) ----------------
#define SM_BQ   0
#define SM_B3   1024
#define SM_W4   1536
#define SM_RED  2048
#define SM_BD   4096
#define BD_STR  1032
#define SM_W3H  (SM_BD + 64 * BD_STR)
#define W3_STR  528
#define SM_W3L  (SM_W3H + 128 * W3_STR)
#define SM_PAIR_TOTAL (SM_W3L + 128 * W3_STR)

__global__ void __launch_bounds__(512, 1)
pair_hmma_kernel(const float* __restrict__ Bq, const float* __restrict__ Bd,
                 const __nv_bfloat16* __restrict__ w3hi, const __nv_bfloat16* __restrict__ w3lo,
                 const float* __restrict__ b3, const float* __restrict__ w4,
                 const float* __restrict__ b4, float* __restrict__ pred)
{
    extern __shared__ char smem[];
    const int t = threadIdx.x, lane = t & 31, wid = t >> 5;
    const int warp_m = wid & 3, warp_n = wid >> 2;
    const int j0 = blockIdx.x * 64;
    const int i0 = blockIdx.y * 8;

    for (int v = t; v < 64 * 128; v += 512) {
        int row = v >> 7, c = v & 127;
        *(float2*)(smem + SM_BD + row * BD_STR + c * 8) =
            ((const float2*)(Bd + (size_t)(j0 + row) * DD))[c];
    }
    for (int v = t; v < 128 * 32; v += 512) {
        int row = v >> 5, c = v & 31;
        *(uint4*)(smem + SM_W3H + row * W3_STR + c * 16) =
            ((const uint4*)(w3hi + (size_t)row * DD))[c];
        *(uint4*)(smem + SM_W3L + row * W3_STR + c * 16) =
            ((const uint4*)(w3lo + (size_t)row * DD))[c];
    }
    if (t < 32) ((uint4*)(smem + SM_B3))[t] = ((const uint4*)b3)[t];
    else if (t < 64) ((uint4*)(smem + SM_W4))[t - 32] = ((const uint4*)w4)[t - 32];
    const float b4v = b4[0];

    const float* b3s = (const float*)(smem + SM_B3);
    const float* w4s = (const float*)(smem + SM_W4);
    float* red = (float*)(smem + SM_RED);

    const int r_lo = warp_m * 16 + (lane >> 2);
    const char* bd_lo = smem + SM_BD + r_lo * BD_STR;
    const char* bd_hi = bd_lo + 8 * BD_STR;
    const int kq = (lane & 3) * 2;
    const int nrow = warp_n * 32 + (lane >> 2);

    for (int il = 0; il < 8; il++) {
        __syncthreads();
        if (t < 64) ((uint4*)(smem + SM_BQ))[t] = ((const uint4*)(Bq + (size_t)(i0 + il) * DD))[t];
        __syncthreads();

        float c[4][4];
        #pragma unroll
        for (int nt = 0; nt < 4; nt++)
            #pragma unroll
            for (int u = 0; u < 4; u++) c[nt][u] = 0.0f;

        #pragma unroll
        for (int ks = 0; ks < 16; ks++) {
            const int kb = ks * 16 + kq;
            float2 q0 = *(const float2*)(smem + SM_BQ + kb * 4);
            float2 q1 = *(const float2*)(smem + SM_BQ + (kb + 8) * 4);
            uint32_t ah[4], al[4];
            {
                float2 d = *(const float2*)(bd_lo + kb * 4);
                split_pack(fmaxf(d.x + q0.x, 0.0f), fmaxf(d.y + q0.y, 0.0f), ah[0], al[0]);
            }
            {
                float2 d = *(const float2*)(bd_hi + kb * 4);
                split_pack(fmaxf(d.x + q0.x, 0.0f), fmaxf(d.y + q0.y, 0.0f), ah[1], al[1]);
            }
            {
                float2 d = *(const float2*)(bd_lo + (kb + 8) * 4);
                split_pack(fmaxf(d.x + q1.x, 0.0f), fmaxf(d.y + q1.y, 0.0f), ah[2], al[2]);
            }
            {
                float2 d = *(const float2*)(bd_hi + (kb + 8) * 4);
                split_pack(fmaxf(d.x + q1.x, 0.0f), fmaxf(d.y + q1.y, 0.0f), ah[3], al[3]);
            }
            #pragma unroll
            for (int nt = 0; nt < 4; nt++) {
                const int roff = (nrow + nt * 8) * W3_STR + kb * 2;
                uint32_t bh0 = *(const uint32_t*)(smem + SM_W3H + roff);
                uint32_t bh1 = *(const uint32_t*)(smem + SM_W3H + roff + 16);
                uint32_t bl0 = *(const uint32_t*)(smem + SM_W3L + roff);
                uint32_t bl1 = *(const uint32_t*)(smem + SM_W3L + roff + 16);
                mma_bf16(c[nt], ah[0], ah[1], ah[2], ah[3], bh0, bh1);
                mma_bf16(c[nt], al[0], al[1], al[2], al[3], bh0, bh1);
                mma_bf16(c[nt], ah[0], ah[1], ah[2], ah[3], bl0, bl1);
            }
        }

        float s_lo = 0.0f, s_hi = 0.0f;
        #pragma unroll
        for (int nt = 0; nt < 4; nt++) {
            int n0 = warp_n * 32 + nt * 8 + (lane & 3) * 2;
            float b30 = b3s[n0], b31 = b3s[n0 + 1];
            float w40 = w4s[n0], w41 = w4s[n0 + 1];
            s_lo += fmaxf(c[nt][0] + b30, 0.0f) * w40 + fmaxf(c[nt][1] + b31, 0.0f) * w41;
            s_hi += fmaxf(c[nt][2] + b30, 0.0f) * w40 + fmaxf(c[nt][3] + b31, 0.0f) * w41;
        }
        s_lo += __shfl_xor_sync(0xFFFFFFFFu, s_lo, 1);
        s_lo += __shfl_xor_sync(0xFFFFFFFFu, s_lo, 2);
        s_hi += __shfl_xor_sync(0xFFFFFFFFu, s_hi, 1);
        s_hi += __shfl_xor_sync(0xFFFFFFFFu, s_hi, 2);
        if ((lane & 3) == 0) {
            red[r_lo * 4 + warp_n] = s_lo;
            red[(r_lo + 8) * 4 + warp_n] = s_hi;
        }
        __syncthreads();
        if (t < 64) {
            float v = red[t * 4] + red[t * 4 + 1] + red[t * 4 + 2] + red[t * 4 + 3] + b4v;
            v = v > 0.0f ? v : 0.0f;
            pred[(size_t)(i0 + il) * ND + j0 + t] = v;
        }
    }
}

// ---------------- host orchestration ----------------
extern "C" void kernel_launch(void* const* d_in, const int* in_sizes, int n_in,
                              void* d_out, int out_size)
{
    const float* qfeat = (const float*)d_in[0];
    const float* dfeat = (const float*)d_in[1];
    const int*   qe    = (const int*)d_in[2];
    const int*   de    = (const int*)d_in[3];
    const int*   qi    = (const int*)d_in[4];
    const int*   di    = (const int*)d_in[5];
    const float* q_w0 = (const float*)d_in[6];
    const float* q_b0 = (const float*)d_in[7];
    const float* q_w1 = (const float*)d_in[8];
    const float* q_b1 = (const float*)d_in[9];
    const float* d_w0 = (const float*)d_in[10];
    const float* d_b0 = (const float*)d_in[11];
    const float* d_w1 = (const float*)d_in[12];
    const float* d_b1 = (const float*)d_in[13];
    const float* w1 = (const float*)d_in[14];
    const float* b1 = (const float*)d_in[15];
    const float* w2 = (const float*)d_in[16];
    const float* b2 = (const float*)d_in[17];
    const float* w3 = (const float*)d_in[18];
    const float* b3 = (const float*)d_in[19];
    const float* w4 = (const float*)d_in[20];
    const float* b4 = (const float*)d_in[21];

    const int EQ = in_sizes[2] / 2;
    const int ED = in_sizes[3] / 2;
    const int EM = in_sizes[4];

    float *qh, *dh, *qB, *dB, *qdeg, *ddeg, *cosw, *Bqp, *Bdp;
    __nv_bfloat16 *wh, *wl;
    cudaGetSymbolAddress((void**)&qh, g_qh);
    cudaGetSymbolAddress((void**)&dh, g_dh);
    cudaGetSymbolAddress((void**)&qB, g_qB);
    cudaGetSymbolAddress((void**)&dB, g_dB);
    cudaGetSymbolAddress((void**)&qdeg, g_qdeg);
    cudaGetSymbolAddress((void**)&ddeg, g_ddeg);
    cudaGetSymbolAddress((void**)&cosw, g_cosw);
    cudaGetSymbolAddress((void**)&Bqp, g_Bq);
    cudaGetSymbolAddress((void**)&Bdp, g_Bd);
    cudaGetSymbolAddress((void**)&wh, g_wh);
    cudaGetSymbolAddress((void**)&wl, g_wl);

    float* out = (float*)d_out;
    float* qOut = out + NQ * ND;                 // layer-1 qf lives in output
    float* dOut = qOut + NQ * CAT;               // layer-1 df lives in output

    cudaFuncSetAttribute(hgemm_kernel, cudaFuncAttributeMaxDynamicSharedMemorySize, HG_SMEM);
    cudaFuncSetAttribute(pair_hmma_kernel, cudaFuncAttributeMaxDynamicSharedMemorySize,
                         SM_PAIR_TOTAL);

    // ---- 1. pack all weights (transpose + bf16 split) ----
    PackArgs pa;
    pa.j[0] = { q_w0,               DD,  DD,  DD,  OFF_QW0 };
    pa.j[1] = { d_w0,               DD,  DD,  DD,  OFF_DW0 };
    pa.j[2] = { q_w1,               CAT, DD,  DD,  OFF_QW1 };
    pa.j[3] = { d_w1,               CAT, DD,  DD,  OFF_DW1 };
    pa.j[4] = { w1,                 CAT, CAT, CAT, OFF_W1T };
    pa.j[5] = { w1 + CAT * CAT,     CAT, CAT, CAT, OFF_W1B };
    pa.j[6] = { w2,                 CAT, DD,  DD,  OFF_W2  };
    pa.j[7] = { w3,                 DD,  128, 128, OFF_W3  };
    pack_kernel<<<dim3(256, 8), 256>>>(pa, wh, wl);

    // ---- 2. degrees (once; identical across layers) ----
    deg_init_kernel<<<5, 256>>>(qdeg, ddeg);
    deg_acc_kernel<<<(EQ + ED + 255) / 256, 256>>>(qe + EQ, EQ, de + ED, ED, qdeg, ddeg);

    const int selfBlocks = (NQ + ND) * 64 / 256;
    const int edgeBlocks = (EQ + ED) * 64 / 256;

    // ---- 3. layer 0 ----
    {
        GemmJob jq = { qfeat, wh + OFF_QW0, wl + OFF_QW0, qh, nullptr, NQ, DD, DD, DD, DD };
        GemmJob jd = { dfeat, wh + OFF_DW0, wl + OFF_DW0, dh, nullptr, ND, DD, DD, DD, DD };
        hgemm_kernel<<<dim3(DD / 64, ND / 128, 2), 256, HG_SMEM>>>(jq, jd);
    }
    self_fused_kernel<<<selfBlocks, 256>>>(qh, dh, qdeg, ddeg, q_b0, d_b0, qB, dB);
    edge_fused_kernel<<<edgeBlocks, 256>>>(qe, qe + EQ, EQ, de, de + ED, ED,
                                           qh, dh, qdeg, ddeg, qB, dB);
    relu_fused_kernel<<<selfBlocks, 256>>>(qB, dB);
    cos_norm_kernel<<<(EM + 7) / 8, 256>>>(qi, di, EM, qB, dB, cosw);
    softmax_kernel<<<1, 1024>>>(cosw, EM);
    cross_agg_kernel<<<EM / 4, 256>>>(qi, di, EM, qB, dB, cosw);

    // ---- 4. layer 1 (outputs written straight into d_out) ----
    {
        GemmJob jq = { qB, wh + OFF_QW1, wl + OFF_QW1, qh, nullptr, NQ, DD, CAT, CAT, DD };
        GemmJob jd = { dB, wh + OFF_DW1, wl + OFF_DW1, dh, nullptr, ND, DD, CAT, CAT, DD };
        hgemm_kernel<<<dim3(DD / 64, ND / 128, 2), 256, HG_SMEM>>>(jq, jd);
    }
    self_fused_kernel<<<selfBlocks, 256>>>(qh, dh, qdeg, ddeg, q_b1, d_b1, qOut, dOut);
    edge_fused_kernel<<<edgeBlocks, 256>>>(qe, qe + EQ, EQ, de, de + ED, ED,
                                           qh, dh, qdeg, ddeg, qOut, dOut);
    relu_fused_kernel<<<selfBlocks, 256>>>(qOut, dOut);
    cos_norm_kernel<<<(EM + 7) / 8, 256>>>(qi, di, EM, qOut, dOut, cosw);
    softmax_kernel<<<1, 1024>>>(cosw, EM);
    cross_agg_kernel<<<EM / 4, 256>>>(qi, di, EM, qOut, dOut, cosw);

    // ---- 5. final scoring (w1/w2 folded: no nonlinearity between them) ----
    {
        GemmJob jq = { qOut, wh + OFF_W1T, wl + OFF_W1T, qB, b1, NQ, CAT, CAT, CAT, CAT };
        GemmJob jd = { dOut, wh + OFF_W1B, wl + OFF_W1B, dB, nullptr, ND, CAT, CAT, CAT, CAT };
        hgemm_kernel<<<dim3(CAT / 64, ND / 128, 2), 256, HG_SMEM>>>(jq, jd);
    }
    {
        GemmJob jq = { qB, wh + OFF_W2, wl + OFF_W2, Bqp, b2, NQ, DD, CAT, CAT, DD };
        GemmJob jd = { dB, wh + OFF_W2, wl + OFF_W2, Bdp, nullptr, ND, DD, CAT, CAT, DD };
        hgemm_kernel<<<dim3(DD / 64, ND / 128, 2), 256, HG_SMEM>>>(jq, jd);
    }

    // ---- 6. pair MLP -> pred ----
    dim3 pg(ND / 64, NQ / 8);
    pair_hmma_kernel<<<pg, 512, SM_PAIR_TOTAL>>>(Bqp, Bdp, wh + OFF_W3, wl + OFF_W3,
                                                 b3, w4, b4, out);
}